// round 6
// baseline (speedup 1.0000x reference)
#include <cuda_runtime.h>

#define Bsz   4
#define Nn    20000
#define Ee    320000
#define CINc  32
#define COUTc 32
#define Kk    16
#define Mm    2

// Scratch
__device__ float  g_fT[Bsz * Nn * CINc];
__device__ float  g_fout[Bsz * Nn * CINc];
__device__ float  g_comb[Mm * Bsz * Nn * 2 * Kk];   // [m][node][k2]{bc,bs}: 128B/row
__device__ float4 g_geo[Bsz * Nn];                  // {x, y, nvx, nvy}
__device__ int    g_hist[Mm * Bsz * Nn];
__device__ int    g_cursor[Mm * Bsz * Nn];
__device__ int4   g_sedge[Mm * Bsz * Ee];           // {tn, sn, sgeo_bits, 0} sorted by tn

__device__ __forceinline__ unsigned f2tf32(float x) {
    unsigned u;
    asm("cvt.rna.tf32.f32 %0, %1;" : "=r"(u) : "f"(x));
    return u;
}

__device__ __forceinline__ void mma_tf32(float c[4], const unsigned a[4], const unsigned b[2]) {
    asm volatile(
        "mma.sync.aligned.m16n8k8.row.col.f32.tf32.tf32.f32 "
        "{%0,%1,%2,%3}, {%4,%5,%6,%7}, {%8,%9}, {%0,%1,%2,%3};"
        : "+f"(c[0]), "+f"(c[1]), "+f"(c[2]), "+f"(c[3])
        : "r"(a[0]), "r"(a[1]), "r"(a[2]), "r"(a[3]), "r"(b[0]), "r"(b[1]));
}

// ---------------------------------------------------------------------------
// Kernel 1: transpose f -> fT, zero f_out + hist, pack comb + geo
// grid (625, B), block (32,8)
// ---------------------------------------------------------------------------
__global__ void prep_kernel(const float* __restrict__ f,
                            const float* __restrict__ bc,
                            const float* __restrict__ bs,
                            const float* __restrict__ nodes,
                            const float* __restrict__ nvec)
{
    __shared__ float tile[32][33];
    const int b   = blockIdx.y;
    const int n0  = blockIdx.x * 32;
    const int tx  = threadIdx.x;
    const int ty  = threadIdx.y;
    const int tid = ty * 32 + tx;

#pragma unroll
    for (int r = 0; r < 4; r++) {
        int ci = ty + 8 * r;
        tile[ci][tx] = f[((long)b * CINc + ci) * Nn + n0 + tx];
    }

    // zero hist (640K threads cover 160K)
    {
        const int gtid = (b * gridDim.x + blockIdx.x) * 256 + tid;
        if (gtid < Mm * Bsz * Nn) g_hist[gtid] = 0;
    }

    // geo pack: 32 nodes per block
    if (tid < 32) {
        const long node = (long)b * Nn + n0 + tid;
        const float2 p  = reinterpret_cast<const float2*>(nodes)[node];
        const float2 nv = reinterpret_cast<const float2*>(nvec)[node];
        g_geo[node] = make_float4(p.x, p.y, nv.x, nv.y);
    }

    // bases repack: 256 threads = 32 nodes x 8 quads
    {
        const int nl = tid >> 3;
        const int pj = tid & 7;
        const long node = (long)b * Nn + n0 + nl;
        const float4 A = *reinterpret_cast<const float4*>(&bc[node * 32 + pj * 4]);
        const float4 B = *reinterpret_cast<const float4*>(&bs[node * 32 + pj * 4]);
        float4* c0 = reinterpret_cast<float4*>(&g_comb[(0L * Bsz * Nn + node) * 32 + pj * 4]);
        float4* c1 = reinterpret_cast<float4*>(&g_comb[(1L * Bsz * Nn + node) * 32 + pj * 4]);
        *c0 = make_float4(A.x, B.x, A.z, B.z);
        *c1 = make_float4(A.y, B.y, A.w, B.w);
    }

    __syncthreads();
#pragma unroll
    for (int r = 0; r < 4; r++) {
        int nl = ty + 8 * r;
        long idx = ((long)b * Nn + n0 + nl) * CINc + tx;
        g_fT[idx]   = tile[tx][nl];
        g_fout[idx] = 0.0f;
    }
}

// ---------------------------------------------------------------------------
// Kernel 2: histogram of targets per (m,b)
// ---------------------------------------------------------------------------
__global__ void __launch_bounds__(256) hist_kernel(const int* __restrict__ de)
{
    const int idx = blockIdx.x * 256 + threadIdx.x;      // b*Ee + e
    const int4 dv = __ldg(&reinterpret_cast<const int4*>(de)[idx]);
    const int b = idx / Ee;
    atomicAdd(&g_hist[(0 * Bsz + b) * Nn + dv.x], 1);
    atomicAdd(&g_hist[(1 * Bsz + b) * Nn + dv.y], 1);
}

// ---------------------------------------------------------------------------
// Kernel 3: exclusive scan per (m,b) segment -> g_cursor
// grid 8 blocks x 1024 threads
// ---------------------------------------------------------------------------
__global__ void __launch_bounds__(1024) scan_kernel()
{
    __shared__ int sh[1024];
    const int seg  = blockIdx.x;          // m*Bsz + b
    const int tid  = threadIdx.x;
    const int base = seg * Nn;
    int carry = 0;

    for (int c = 0; c < (Nn + 1023) / 1024; c++) {
        const int i = c * 1024 + tid;
        const int v = (i < Nn) ? g_hist[base + i] : 0;
        sh[tid] = v;
        __syncthreads();
#pragma unroll
        for (int off = 1; off < 1024; off <<= 1) {
            int t = (tid >= off) ? sh[tid - off] : 0;
            __syncthreads();
            sh[tid] += t;
            __syncthreads();
        }
        if (i < Nn) g_cursor[base + i] = carry + sh[tid] - v;
        carry += sh[1023];
        __syncthreads();
    }
}

// ---------------------------------------------------------------------------
// Kernel 4: scatter edges into target-sorted bins, computing sgeo
// ---------------------------------------------------------------------------
__global__ void __launch_bounds__(256) scatter_kernel(
    const int*   __restrict__ de,
    const float* __restrict__ nodew)
{
    const int idx = blockIdx.x * 256 + threadIdx.x;      // b*Ee + e
    const int4 dv = __ldg(&reinterpret_cast<const int4*>(de)[idx]);
    const int b = idx / Ee;

#pragma unroll
    for (int m = 0; m < 2; m++) {
        const int t = m ? dv.y : dv.x;
        const int s = m ? dv.w : dv.z;
        const int tn = b * Nn + t;
        const int sn = b * Nn + s;
        const float4 gt = g_geo[tn];
        const float4 gs = g_geo[sn];
        const float dx = gt.x - gs.x, dy = gt.y - gs.y;
        const float r2 = fmaf(dx, dx, fmaf(dy, dy, 1e-6f));
        const float gr = fmaf(dx, gs.z, dy * gs.w) / r2;
        const float sgeo = gr * __ldg(&nodew[(long)idx * 2 + m]);
        const int pos = atomicAdd(&g_cursor[(m * Bsz + b) * Nn + t], 1);
        g_sedge[((long)(m * Bsz + b)) * Ee + pos] =
            make_int4(tn, sn, __float_as_int(sgeo), 0);
    }
}

// ---------------------------------------------------------------------------
// W matrix element: Wmat[r][c], c<16 -> 2*wc[r][c], c>=16 -> 2*ws[r][c-16]
// ---------------------------------------------------------------------------
__device__ __forceinline__ float loadW(const float* __restrict__ wc,
                                       const float* __restrict__ ws,
                                       int r, int c, int m)
{
    return (c < 16) ? 2.0f * __ldg(&wc[r * 32 + c * 2 + m])
                    : 2.0f * __ldg(&ws[r * 32 + (c - 16) * 2 + m]);
}

// ---------------------------------------------------------------------------
// Kernel 5: edge scatter on sorted records, mma edge-weights, segmented RED
// ---------------------------------------------------------------------------
__global__ void __launch_bounds__(128) edge_kernel(
    const float* __restrict__ wc,
    const float* __restrict__ ws,
    const float* __restrict__ w0)
{
    __shared__ float pqs[4][32][36];
    __shared__ int2  nsb[4][32];
    __shared__ float sgb[4][32];

    const int lane = threadIdx.x & 31;
    const int wid  = threadIdx.x >> 5;
    float (*pq)[36] = pqs[wid];

    const int gw = blockIdx.x * 4 + wid;
    const int WPM = 5000;
    const int m      = gw / WPM;
    const int w_in_m = gw % WPM;

    const int gid = lane >> 2;
    const int tq  = lane & 3;

    unsigned afr[2][4][4];
#pragma unroll
    for (int mt = 0; mt < 2; mt++)
#pragma unroll
        for (int ks = 0; ks < 4; ks++) {
            const int r0 = mt * 16 + gid, r1 = r0 + 8;
            const int c0 = ks * 8 + tq,  c1 = c0 + 4;
            afr[mt][ks][0] = f2tf32(loadW(wc, ws, r0, c0, m));
            afr[mt][ks][1] = f2tf32(loadW(wc, ws, r1, c0, m));
            afr[mt][ks][2] = f2tf32(loadW(wc, ws, r0, c1, m));
            afr[mt][ks][3] = f2tf32(loadW(wc, ws, r1, c1, m));
        }

    const int g4 = (lane & 7) * 4;
    const float w00 = __ldg(&w0[(g4 + 0) * 2 + m]) + 1.0f;
    const float w01 = __ldg(&w0[(g4 + 1) * 2 + m]) + 1.0f;
    const float w02 = __ldg(&w0[(g4 + 2) * 2 + m]) + 1.0f;
    const float w03 = __ldg(&w0[(g4 + 3) * 2 + m]) + 1.0f;

    const float* comb   = g_comb + (long)m * Bsz * Nn * 32;
    const int4*  sebase = g_sedge + (long)m * Bsz * Ee;

    const int ph = (lane >> 4) & 1;
    const int pp = (lane >> 3) & 1;
    const int pj = lane & 7;
    const int lg = lane >> 3;          // epilogue lane-group: 8 consecutive edges

    for (int tidx = w_in_m; tidx < 4 * (Ee / 32); tidx += WPM) {
        const int b  = tidx / (Ee / 32);
        const int e0 = (tidx % (Ee / 32)) * 32;

        // ---- record load: lane = edge ----
        const int4 rec = __ldg(&sebase[(long)b * Ee + e0 + lane]);
        nsb[wid][lane] = make_int2(rec.x, rec.y);
        sgb[wid][lane] = __int_as_float(rec.z);
        __syncwarp();

        // ---- PQ phase ----
#pragma unroll
        for (int pr = 0; pr < 16; pr++) {
            const int e    = pr * 2 + ph;
            const int node = pp ? nsb[wid][e].y : nsb[wid][e].x;
            const float4 A = *reinterpret_cast<const float4*>(&comb[(long)node * 32 + pj * 4]);
            const float a0 = A.x, b0 = A.y, a1 = A.z, b1 = A.w;
            const float a0o = __shfl_xor_sync(0xffffffffu, a0, 8);
            const float a1o = __shfl_xor_sync(0xffffffffu, a1, 8);
            const float b0o = __shfl_xor_sync(0xffffffffu, b0, 8);
            const float b1o = __shfl_xor_sync(0xffffffffu, b1, 8);
            const float r0 = pp ? fmaf(b0, a0o, -(a0 * b0o))
                                : fmaf(a0, a0o,  (b0 * b0o));
            const float r1 = pp ? fmaf(b1, a1o, -(a1 * b1o))
                                : fmaf(a1, a1o,  (b1 * b1o));
            float2* dst = reinterpret_cast<float2*>(&pq[e][pp * 16 + 2 * pj]);
            *dst = make_float2(__uint_as_float(f2tf32(r0)),
                               __uint_as_float(f2tf32(r1)));
        }
        __syncwarp();

        // ---- MMA phase ----
#pragma unroll
        for (int nt = 0; nt < 4; nt++) {
            unsigned bfr[4][2];
#pragma unroll
            for (int ks = 0; ks < 4; ks++) {
                bfr[ks][0] = __float_as_uint(pq[nt * 8 + gid][ks * 8 + tq]);
                bfr[ks][1] = __float_as_uint(pq[nt * 8 + gid][ks * 8 + tq + 4]);
            }
            __syncwarp();
#pragma unroll
            for (int mt = 0; mt < 2; mt++) {
                float acc[4] = {0.0f, 0.0f, 0.0f, 0.0f};
#pragma unroll
                for (int ks = 0; ks < 4; ks++)
                    mma_tf32(acc, afr[mt][ks], bfr[ks]);
                const int ch = mt * 16 + gid;
                const int ed = nt * 8 + 2 * tq;
                pq[ed][ch]         = acc[0];
                pq[ed + 1][ch]     = acc[1];
                pq[ed][ch + 8]     = acc[2];
                pq[ed + 1][ch + 8] = acc[3];
            }
        }
        __syncwarp();

        // ---- epilogue: lane-group lg handles edges 8lg..8lg+7 (sorted by tn),
        //      register-accumulate per target segment, flush one v4 RED ----
        {
            float ax = 0.f, ay = 0.f, az = 0.f, aw = 0.f;
            int cur = -1;
#pragma unroll
            for (int it = 0; it < 8; it++) {
                const int e    = lg * 8 + it;
                const int2 ns  = nsb[wid][e];
                const float sg = sgb[wid][e];
                if (ns.x != cur) {
                    if (cur >= 0) {
                        float* dst = &g_fout[(long)cur * 32 + g4];
                        asm volatile(
                            "red.global.add.v4.f32 [%0], {%1, %2, %3, %4};"
                            :: "l"(dst), "f"(ax), "f"(ay), "f"(az), "f"(aw)
                            : "memory");
                    }
                    ax = ay = az = aw = 0.f;
                    cur = ns.x;
                }
                const float4 fs = *reinterpret_cast<const float4*>(&g_fT[(long)ns.y * 32 + g4]);
                const float4 ew = *reinterpret_cast<const float4*>(&pq[e][g4]);
                ax = fmaf((w00 + ew.x) * fs.x, sg, ax);
                ay = fmaf((w01 + ew.y) * fs.y, sg, ay);
                az = fmaf((w02 + ew.z) * fs.z, sg, az);
                aw = fmaf((w03 + ew.w) * fs.w, sg, aw);
            }
            float* dst = &g_fout[(long)cur * 32 + g4];
            asm volatile(
                "red.global.add.v4.f32 [%0], {%1, %2, %3, %4};"
                :: "l"(dst), "f"(ax), "f"(ay), "f"(az), "f"(aw)
                : "memory");
        }
        __syncwarp();
    }
}

// ---------------------------------------------------------------------------
// Kernel 6: out[b,o,n] = sum_i w[o,i] * f_out[b,n,i] + bias[o]
// ---------------------------------------------------------------------------
__global__ void __launch_bounds__(256) out_kernel(
    const float* __restrict__ wk,
    const float* __restrict__ bias,
    float* __restrict__ out)
{
    __shared__ float fsm[32][33];
    __shared__ float wsm[COUTc][CINc];

    const int b   = blockIdx.y;
    const int n0  = blockIdx.x * 32;
    const int tid = threadIdx.x;

    for (int j = tid; j < COUTc * CINc; j += 256)
        wsm[j / CINc][j % CINc] = wk[j];

#pragma unroll
    for (int j = 0; j < 4; j++) {
        int idx = j * 256 + tid;
        int nl = idx >> 5, i = idx & 31;
        fsm[nl][i] = g_fout[((long)b * Nn + n0 + nl) * CINc + i];
    }
    __syncthreads();

#pragma unroll
    for (int j = 0; j < 4; j++) {
        int idx = j * 256 + tid;
        int o = idx >> 5, nl = idx & 31;
        float acc = bias[o];
#pragma unroll
        for (int i = 0; i < CINc; i++)
            acc = fmaf(wsm[o][i], fsm[nl][i], acc);
        out[((long)b * COUTc + o) * Nn + n0 + nl] = acc;
    }
}

// ---------------------------------------------------------------------------
extern "C" void kernel_launch(void* const* d_in, const int* in_sizes, int n_in,
                              void* d_out, int out_size)
{
    const float* f    = (const float*)d_in[0];
    const float* bc   = (const float*)d_in[1];
    const float* bs   = (const float*)d_in[2];
    const float* nodes= (const float*)d_in[4];
    const float* nvec = (const float*)d_in[5];
    const int*   de   = (const int*)  d_in[6];
    const float* nw   = (const float*)d_in[7];
    const float* wc   = (const float*)d_in[8];
    const float* ws   = (const float*)d_in[9];
    const float* w0   = (const float*)d_in[10];
    const float* wk   = (const float*)d_in[11];
    const float* wb   = (const float*)d_in[12];
    float* out = (float*)d_out;

    prep_kernel<<<dim3(Nn / 32, Bsz), dim3(32, 8)>>>(f, bc, bs, nodes, nvec);
    hist_kernel<<<(Bsz * Ee) / 256, 256>>>(de);
    scan_kernel<<<Mm * Bsz, 1024>>>();
    scatter_kernel<<<(Bsz * Ee) / 256, 256>>>(de, nw);
    edge_kernel<<<2500, 128>>>(wc, ws, w0);
    out_kernel<<<dim3(Nn / 32, Bsz), 256>>>(wk, wb, out);
}

// round 7
// speedup vs baseline: 1.4704x; 1.4704x over previous
#include <cuda_runtime.h>

#define Bsz   4
#define Nn    20000
#define Ee    320000
#define CINc  32
#define COUTc 32
#define Kk    16
#define Mm    2

// Scratch
__device__ float  g_fT[Bsz * Nn * CINc];
__device__ float  g_fout[Bsz * Nn * CINc];
__device__ float  g_comb[Mm * Bsz * Nn * 2 * Kk];   // [m][node]{bc,bs interleaved}: 128B/row
__device__ float4 g_geo[Bsz * Nn];                  // {x, y, nvx, nvy}

__device__ __forceinline__ unsigned f2tf32(float x) {
    unsigned u;
    asm("cvt.rna.tf32.f32 %0, %1;" : "=r"(u) : "f"(x));
    return u;
}

__device__ __forceinline__ void mma_tf32(float c[4], const unsigned a[4], const unsigned b[2]) {
    asm volatile(
        "mma.sync.aligned.m16n8k8.row.col.f32.tf32.tf32.f32 "
        "{%0,%1,%2,%3}, {%4,%5,%6,%7}, {%8,%9}, {%0,%1,%2,%3};"
        : "+f"(c[0]), "+f"(c[1]), "+f"(c[2]), "+f"(c[3])
        : "r"(a[0]), "r"(a[1]), "r"(a[2]), "r"(a[3]), "r"(b[0]), "r"(b[1]));
}

// ---------------------------------------------------------------------------
// Kernel 1: transpose f -> fT, zero f_out, pack comb + geo
// grid (625, B), block (32,8)
// ---------------------------------------------------------------------------
__global__ void prep_kernel(const float* __restrict__ f,
                            const float* __restrict__ bc,
                            const float* __restrict__ bs,
                            const float* __restrict__ nodes,
                            const float* __restrict__ nvec)
{
    __shared__ float tile[32][33];
    const int b   = blockIdx.y;
    const int n0  = blockIdx.x * 32;
    const int tx  = threadIdx.x;
    const int ty  = threadIdx.y;
    const int tid = ty * 32 + tx;

#pragma unroll
    for (int r = 0; r < 4; r++) {
        int ci = ty + 8 * r;
        tile[ci][tx] = f[((long)b * CINc + ci) * Nn + n0 + tx];
    }

    // geo pack: 32 nodes per block
    if (tid < 32) {
        const long node = (long)b * Nn + n0 + tid;
        const float2 p  = reinterpret_cast<const float2*>(nodes)[node];
        const float2 nv = reinterpret_cast<const float2*>(nvec)[node];
        g_geo[node] = make_float4(p.x, p.y, nv.x, nv.y);
    }

    // bases repack: 256 threads = 32 nodes x 8 quads
    {
        const int nl = tid >> 3;
        const int pj = tid & 7;
        const long node = (long)b * Nn + n0 + nl;
        const float4 A = *reinterpret_cast<const float4*>(&bc[node * 32 + pj * 4]);
        const float4 B = *reinterpret_cast<const float4*>(&bs[node * 32 + pj * 4]);
        float4* c0 = reinterpret_cast<float4*>(&g_comb[(0L * Bsz * Nn + node) * 32 + pj * 4]);
        float4* c1 = reinterpret_cast<float4*>(&g_comb[(1L * Bsz * Nn + node) * 32 + pj * 4]);
        *c0 = make_float4(A.x, B.x, A.z, B.z);   // m = 0
        *c1 = make_float4(A.y, B.y, A.w, B.w);   // m = 1
    }

    __syncthreads();
#pragma unroll
    for (int r = 0; r < 4; r++) {
        int nl = ty + 8 * r;
        long idx = ((long)b * Nn + n0 + nl) * CINc + tx;
        g_fT[idx]   = tile[tx][nl];
        g_fout[idx] = 0.0f;
    }
}

// ---------------------------------------------------------------------------
// W matrix element: Wmat[r][c], c<16 -> 2*wc[r][c], c>=16 -> 2*ws[r][c-16]
// ---------------------------------------------------------------------------
__device__ __forceinline__ float loadW(const float* __restrict__ wc,
                                       const float* __restrict__ ws,
                                       int r, int c, int m)
{
    return (c < 16) ? 2.0f * __ldg(&wc[r * 32 + c * 2 + m])
                    : 2.0f * __ldg(&ws[r * 32 + (c - 16) * 2 + m]);
}

// ---------------------------------------------------------------------------
// Kernel 2: edge scatter, mma-based. One warp per 32-edge tile.
// SHFL-free PQ, split smem buffers, 4 syncwarps/tile.
// ---------------------------------------------------------------------------
__global__ void __launch_bounds__(128) edge_kernel(
    const int*   __restrict__ de,
    const float* __restrict__ nodew,
    const float* __restrict__ wc,
    const float* __restrict__ ws,
    const float* __restrict__ w0)
{
    __shared__ __align__(16) float pqin[4][32][36];   // [edge][k]: P 0..15, Q 16..31
    __shared__ __align__(16) float ewout[4][32][36];  // [edge][ch]
    __shared__ int2  nsb[4][32];
    __shared__ float sgb[4][32];

    const int lane = threadIdx.x & 31;
    const int wid  = threadIdx.x >> 5;
    float (*pin)[36]  = pqin[wid];
    float (*pout)[36] = ewout[wid];

    const int gw = blockIdx.x * 4 + wid;
    const int WPM = 5000;
    const int m      = gw / WPM;
    const int w_in_m = gw % WPM;

    const int gid = lane >> 2;
    const int tq  = lane & 3;

    // persistent A fragments: W (32x32) tf32
    unsigned afr[2][4][4];
#pragma unroll
    for (int mt = 0; mt < 2; mt++)
#pragma unroll
        for (int ks = 0; ks < 4; ks++) {
            const int r0 = mt * 16 + gid, r1 = r0 + 8;
            const int c0 = ks * 8 + tq,  c1 = c0 + 4;
            afr[mt][ks][0] = f2tf32(loadW(wc, ws, r0, c0, m));
            afr[mt][ks][1] = f2tf32(loadW(wc, ws, r1, c0, m));
            afr[mt][ks][2] = f2tf32(loadW(wc, ws, r0, c1, m));
            afr[mt][ks][3] = f2tf32(loadW(wc, ws, r1, c1, m));
        }

    const int g4 = (lane & 7) * 4;
    const float w00 = __ldg(&w0[(g4 + 0) * 2 + m]) + 1.0f;
    const float w01 = __ldg(&w0[(g4 + 1) * 2 + m]) + 1.0f;
    const float w02 = __ldg(&w0[(g4 + 2) * 2 + m]) + 1.0f;
    const float w03 = __ldg(&w0[(g4 + 3) * 2 + m]) + 1.0f;

    const float* comb = g_comb + (long)m * Bsz * Nn * 32;
    const int4*  de4  = reinterpret_cast<const int4*>(de);

    const int e4 = lane >> 3;      // PQ: edge-quarter 0..3
    const int pj = lane & 7;       // PQ: quad within 128B row
    const int lg = lane >> 3;      // epilogue lane-group

    for (int tidx = w_in_m; tidx < 4 * (Ee / 32); tidx += WPM) {
        const int b  = tidx / (Ee / 32);
        const int e0 = (tidx % (Ee / 32)) * 32;

        // ---- geometry: lane = edge ----
        const long eb = (long)b * Ee + e0 + lane;
        const int4 dv = __ldg(&de4[eb]);
        const int tn = b * Nn + (m ? dv.y : dv.x);
        const int sn = b * Nn + (m ? dv.w : dv.z);
        const float4 gt = g_geo[tn];
        const float4 gs = g_geo[sn];
        const float dx = gt.x - gs.x, dy = gt.y - gs.y;
        const float r2 = fmaf(dx, dx, fmaf(dy, dy, 1e-6f));
        const float gr = fmaf(dx, gs.z, dy * gs.w) / r2;
        nsb[wid][lane] = make_int2(tn, sn);
        sgb[wid][lane] = gr * __ldg(&nodew[eb * 2 + m]);
        __syncwarp();

        // ---- PQ phase: shfl-free; lane loads target+source quads ----
#pragma unroll
        for (int pr = 0; pr < 8; pr++) {
            const int e   = pr * 4 + e4;
            const int2 ns = nsb[wid][e];
            const float4 T = *reinterpret_cast<const float4*>(&comb[(long)ns.x * 32 + pj * 4]);
            const float4 S = *reinterpret_cast<const float4*>(&comb[(long)ns.y * 32 + pj * 4]);
            // T=(bc_t0,bs_t0,bc_t1,bs_t1), S likewise for source
            const float P0 = fmaf(T.x, S.x,  T.y * S.y);
            const float Q0 = fmaf(T.x, S.y, -(T.y * S.x));
            const float P1 = fmaf(T.z, S.z,  T.w * S.w);
            const float Q1 = fmaf(T.z, S.w, -(T.w * S.z));
            *reinterpret_cast<float2*>(&pin[e][2 * pj]) =
                make_float2(__uint_as_float(f2tf32(P0)), __uint_as_float(f2tf32(P1)));
            *reinterpret_cast<float2*>(&pin[e][16 + 2 * pj]) =
                make_float2(__uint_as_float(f2tf32(Q0)), __uint_as_float(f2tf32(Q1)));
        }
        __syncwarp();

        // ---- MMA phase: EW[32ch][32edges] = W * PQ^T (pqin -> ewout) ----
#pragma unroll
        for (int nt = 0; nt < 4; nt++) {
            unsigned bfr[4][2];
#pragma unroll
            for (int ks = 0; ks < 4; ks++) {
                bfr[ks][0] = __float_as_uint(pin[nt * 8 + gid][ks * 8 + tq]);
                bfr[ks][1] = __float_as_uint(pin[nt * 8 + gid][ks * 8 + tq + 4]);
            }
#pragma unroll
            for (int mt = 0; mt < 2; mt++) {
                float acc[4] = {0.0f, 0.0f, 0.0f, 0.0f};
#pragma unroll
                for (int ks = 0; ks < 4; ks++)
                    mma_tf32(acc, afr[mt][ks], bfr[ks]);
                const int ch = mt * 16 + gid;
                const int ed = nt * 8 + 2 * tq;
                pout[ed][ch]         = acc[0];
                pout[ed + 1][ch]     = acc[1];
                pout[ed][ch + 8]     = acc[2];
                pout[ed + 1][ch + 8] = acc[3];
            }
        }
        __syncwarp();

        // ---- epilogue: lane = (edge-subgroup, 4-channel group), v4 atomics ----
#pragma unroll
        for (int it = 0; it < 8; it++) {
            const int e    = it * 4 + lg;
            const int2 ns  = nsb[wid][e];
            const float sg = sgb[wid][e];
            const float4 fs = *reinterpret_cast<const float4*>(&g_fT[(long)ns.y * 32 + g4]);
            const float4 ew = *reinterpret_cast<const float4*>(&pout[e][g4]);
            const float v0 = (w00 + ew.x) * fs.x * sg;
            const float v1 = (w01 + ew.y) * fs.y * sg;
            const float v2 = (w02 + ew.z) * fs.z * sg;
            const float v3 = (w03 + ew.w) * fs.w * sg;
            float* dst = &g_fout[(long)ns.x * 32 + g4];
            asm volatile(
                "red.global.add.v4.f32 [%0], {%1, %2, %3, %4};"
                :: "l"(dst), "f"(v0), "f"(v1), "f"(v2), "f"(v3)
                : "memory");
        }
        __syncwarp();   // WAR: nsb/sgb reused next iteration
    }
}

// ---------------------------------------------------------------------------
// Kernel 3: out[b,o,n] = sum_i w[o,i] * f_out[b,n,i] + bias[o]
// ---------------------------------------------------------------------------
__global__ void __launch_bounds__(256) out_kernel(
    const float* __restrict__ wk,
    const float* __restrict__ bias,
    float* __restrict__ out)
{
    __shared__ float fsm[32][33];
    __shared__ float wsm[COUTc][CINc];

    const int b   = blockIdx.y;
    const int n0  = blockIdx.x * 32;
    const int tid = threadIdx.x;

    for (int j = tid; j < COUTc * CINc; j += 256)
        wsm[j / CINc][j % CINc] = wk[j];

#pragma unroll
    for (int j = 0; j < 4; j++) {
        int idx = j * 256 + tid;
        int nl = idx >> 5, i = idx & 31;
        fsm[nl][i] = g_fout[((long)b * Nn + n0 + nl) * CINc + i];
    }
    __syncthreads();

#pragma unroll
    for (int j = 0; j < 4; j++) {
        int idx = j * 256 + tid;
        int o = idx >> 5, nl = idx & 31;
        float acc = bias[o];
#pragma unroll
        for (int i = 0; i < CINc; i++)
            acc = fmaf(wsm[o][i], fsm[nl][i], acc);
        out[((long)b * COUTc + o) * Nn + n0 + nl] = acc;
    }
}

// ---------------------------------------------------------------------------
extern "C" void kernel_launch(void* const* d_in, const int* in_sizes, int n_in,
                              void* d_out, int out_size)
{
    const float* f    = (const float*)d_in[0];
    const float* bc   = (const float*)d_in[1];
    const float* bs   = (const float*)d_in[2];
    const float* nodes= (const float*)d_in[4];
    const float* nvec = (const float*)d_in[5];
    const int*   de   = (const int*)  d_in[6];
    const float* nw   = (const float*)d_in[7];
    const float* wc   = (const float*)d_in[8];
    const float* ws   = (const float*)d_in[9];
    const float* w0   = (const float*)d_in[10];
    const float* wk   = (const float*)d_in[11];
    const float* wb   = (const float*)d_in[12];
    float* out = (float*)d_out;

    prep_kernel<<<dim3(Nn / 32, Bsz), dim3(32, 8)>>>(f, bc, bs, nodes, nvec);
    edge_kernel<<<2500, 128>>>(de, nw, wc, ws, w0);
    out_kernel<<<dim3(Nn / 32, Bsz), 256>>>(wk, wb, out);
}